// round 8
// baseline (speedup 1.0000x reference)
#include <cuda_runtime.h>
#include <math.h>
#include <cstddef>

// B=256, T=64, D=16, S=64, H=128, O=8
#define NTHR 512
#define PREPT 256
#define KCP 28         // cached k-PAIRS (56 k-rows) of this CTA's Wf3 n-half

// Pair-packed Wf3: g_Wf3P[(kp*1024 + n)*2 + r] = Wf3[n*128 + 2*kp + r]  (512 KB)
__device__ __align__(16) float g_Wf3P[64 * 1024 * 2];

__constant__ float cC[6]  = {0.0f, 0.161f, 0.327f, 0.9f, 0.9800255409045097f, 1.0f};
__constant__ float cBw[6] = {0.09646076681806523f, 0.01f, 0.4798896504144996f,
                             1.379008574103742f, -3.290069515436081f, 2.324710524099774f};
__constant__ float cA[6][5] = {
    {0.f, 0.f, 0.f, 0.f, 0.f},
    {0.161f, 0.f, 0.f, 0.f, 0.f},
    {-0.008480655492356989f, 0.335480655492357f, 0.f, 0.f, 0.f},
    {2.8971530571054935f, -6.359448489975075f, 4.3622954328695815f, 0.f, 0.f},
    {5.325864828439257f, -11.748883564062828f, 7.4955393428898365f, -0.09249506636175525f, 0.f},
    {5.86145544294642f, -12.92096931784711f, 8.159367898576159f, -0.071584973281401f,
     -0.028269050394068383f}};

struct __align__(16) Smem {
    float wc[KCP * 512 * 2];   // cached Wf3 pairs [kp][n_local][2]   114688 B
    float Wf2P[64 * 128 * 2];  // [kp][i][2]                           65536 B
    float Wf1P[32 * 128 * 2];  // [kp][i][2]                           32768 B
    float h2[4][128];          // plain h2, all 4 rows                  2048 B
    float h1[4][128];          // plain h1, all 4 rows                  2048 B
    float yj[4][64];           // plain yj, all 4 rows                  1024 B
    float y[4][64];            //                                       1024 B
    float ks[6][4][64];        // replicated (peer half via st.async)   6144 B
    float dx[4][16];
    float cbv[4][16];
    float ccv[4][16];
    float cdv[4][16];
    float bf1v[128];
    float bf2v[128];
    float bf3loc[512];
    unsigned long long ks_mbar;
};  // 229392 B

// ---------- helpers ----------
__device__ __forceinline__ unsigned long long fma2(unsigned long long a,
                                                   unsigned long long b,
                                                   unsigned long long c) {
    unsigned long long d;
    asm("fma.rn.f32x2 %0, %1, %2, %3;" : "=l"(d) : "l"(a), "l"(b), "l"(c));
    return d;
}
__device__ __forceinline__ float2 u2f(unsigned long long v) {
    float2 r;
    asm("mov.b64 {%0, %1}, %2;" : "=f"(r.x), "=f"(r.y) : "l"(v));
    return r;
}
__device__ __forceinline__ unsigned long long ldg64(const float* p) {
    unsigned long long v;
    asm("ld.global.nc.u64 %0, [%1];" : "=l"(v) : "l"(p));
    return v;
}
__device__ __forceinline__ unsigned smem_u32(const void* p) {
    unsigned r;
    asm("{ .reg .u64 t; cvta.to.shared.u64 t, %1; cvt.u32.u64 %0, t; }"
        : "=r"(r) : "l"(p));
    return r;
}
__device__ __forceinline__ unsigned long long lds64(unsigned a) {
    unsigned long long v;
    asm("ld.shared.u64 %0, [%1];" : "=l"(v) : "r"(a));
    return v;
}
__device__ __forceinline__ void lds_v2u64(unsigned a, unsigned long long& x,
                                          unsigned long long& y) {
    asm volatile("ld.shared.v2.u64 {%0, %1}, [%2];" : "=l"(x), "=l"(y) : "r"(a));
}
__device__ __forceinline__ unsigned mapa_u32(unsigned laddr, unsigned peer) {
    unsigned r;
    asm("mapa.shared::cluster.u32 %0, %1, %2;" : "=r"(r) : "r"(laddr), "r"(peer));
    return r;
}
__device__ __forceinline__ void mbar_init(unsigned a, unsigned cnt) {
    asm volatile("mbarrier.init.shared.b64 [%0], %1;" :: "r"(a), "r"(cnt) : "memory");
}
__device__ __forceinline__ void mbar_expect_tx(unsigned a, unsigned bytes) {
    asm volatile("mbarrier.arrive.expect_tx.shared.b64 _, [%0], %1;"
                 :: "r"(a), "r"(bytes) : "memory");
}
__device__ __forceinline__ void mbar_wait(unsigned a, unsigned parity) {
    asm volatile(
        "{\n\t.reg .pred P;\n"
        "LW_%=:\n\t"
        "mbarrier.try_wait.parity.acquire.cta.shared::cta.b64 P, [%0], %1, 0x989680;\n\t"
        "@P bra LD_%=;\n\t"
        "bra LW_%=;\n"
        "LD_%=:\n\t}"
        :: "r"(a), "r"(parity) : "memory");
}
__device__ __forceinline__ void st_async32(unsigned dst, float v, unsigned mbar) {
    asm volatile("st.async.shared::cluster.mbarrier::complete_tx::bytes.b32 [%0], %1, [%2];"
                 :: "r"(dst), "f"(v), "r"(mbar) : "memory");
}
__device__ __forceinline__ float softplus_f(float x) {
    return fmaxf(x, 0.0f) + log1pf(__expf(-fabsf(x)));
}
__device__ __forceinline__ float tanh_fast(float x) {
    float e = __expf(2.0f * x);
    return 1.0f - 2.0f / (e + 1.0f);
}

__global__ void __launch_bounds__(PREPT, 1) prep_kernel(const float* __restrict__ Wf3) {
    int idx = blockIdx.x * PREPT + threadIdx.x;   // 512 blocks x 256 = 131072
    int kp = idx >> 11;
    int rem = idx & 2047;
    int n = rem >> 1;
    int r = rem & 1;
    g_Wf3P[idx] = Wf3[n * 128 + 2 * kp + r];
}

__global__ void __launch_bounds__(NTHR, 1) __cluster_dims__(2, 1, 1) cde_kernel(
    const float* __restrict__ ts,
    const float* __restrict__ coeff_d, const float* __restrict__ coeff_c,
    const float* __restrict__ coeff_b, const float* __restrict__ coeff_a,
    const float* __restrict__ Wi1, const float* __restrict__ bi1,
    const float* __restrict__ Wi2, const float* __restrict__ bi2,
    const float* __restrict__ Wf1, const float* __restrict__ bf1,
    const float* __restrict__ Wf2, const float* __restrict__ bf2,
    const float* __restrict__ bf3,
    const float* __restrict__ Wr, const float* __restrict__ br,
    float* __restrict__ out)
{
    extern __shared__ char smraw[];
    Smem& sm = *reinterpret_cast<Smem*>(smraw);
    const int tid = threadIdx.x;
    unsigned rank;
    asm("mov.u32 %0, %%cluster_ctarank;" : "=r"(rank));
    const unsigned peer = rank ^ 1u;
    const int b0g = (blockIdx.x >> 1) * 4;   // 4 batch rows per cluster

    const unsigned sbase = smem_u32(smraw);
    const unsigned my_ksmbar = sbase + (unsigned)offsetof(Smem, ks_mbar);
    const unsigned peer_ksmbar = mapa_u32(my_ksmbar, peer);
    const unsigned peer_ksbase = mapa_u32(sbase + (unsigned)offsetof(Smem, ks), peer);

    if (tid == 0) mbar_init(my_ksmbar, 1);

    // ---- one-time init ----
    // Wf1P[(kp*128+i)*2+r] = Wf1[i*64 + 2kp + r]
    for (int idx = tid; idx < 32 * 128 * 2; idx += NTHR) {
        int kp = idx >> 8, rem = idx & 255, i = rem >> 1, r = rem & 1;
        sm.Wf1P[idx] = Wf1[i * 64 + 2 * kp + r];
    }
    // Wf2P[(kp*128+i)*2+r] = Wf2[i*128 + 2kp + r]
    for (int idx = tid; idx < 64 * 128 * 2; idx += NTHR) {
        int kp = idx >> 8, rem = idx & 255, i = rem >> 1, r = rem & 1;
        sm.Wf2P[idx] = Wf2[i * 128 + 2 * kp + r];
    }
    // wc[kp][n_local][2] from g_Wf3P (this CTA's n-half)
    for (int idx = tid; idx < KCP * 1024; idx += NTHR) {
        int kp = idx >> 10, rem = idx & 1023;
        sm.wc[idx] = g_Wf3P[kp * 2048 + rank * 1024 + rem];
    }
    if (tid < 128) { sm.bf1v[tid] = bf1[tid]; sm.bf2v[tid] = bf2[tid]; }
    for (int idx = tid; idx < 512; idx += NTHR) sm.bf3loc[idx] = bf3[rank * 512 + idx];
    if (tid < 64) {  // x0 = coeff_a[:,0,:]
        int b = tid >> 4, d = tid & 15;
        sm.dx[b][d] = coeff_a[(b0g + b) * 63 * 16 + d];
    }
    __syncthreads();
    // peer mbarrier must be live before any st.async
    asm volatile("barrier.cluster.arrive.aligned;" ::: "memory");
    asm volatile("barrier.cluster.wait.aligned;" ::: "memory");

    // ---- y0 = softplus(x0 @ Wi1^T + bi1) @ Wi2^T + bi2 ----
    if (tid < 256) {
        int b = tid >> 6;
        #pragma unroll
        for (int q = 0; q < 2; ++q) {
            int jj = ((tid & 63) << 1) + q;
            float acc = bi1[jj];
            #pragma unroll
            for (int d = 0; d < 16; ++d) acc += sm.dx[b][d] * Wi1[jj * 16 + d];
            sm.h1[b][jj] = softplus_f(acc);
        }
    }
    __syncthreads();
    if (tid < 256) {
        int b = tid >> 6, s = tid & 63;
        float acc = bi2[s];
        #pragma unroll 8
        for (int k = 0; k < 128; ++k) acc += sm.h1[b][k] * Wi2[s * 128 + k];
        sm.y[b][s] = acc;
    }
    __syncthreads();
    if (tid < 16) {
        int bl = tid >> 3, o = tid & 7;
        int row = (int)rank * 2 + bl;
        float acc = br[o];
        #pragma unroll 8
        for (int s2 = 0; s2 < 64; ++s2) acc += sm.y[row][s2] * Wr[o * 64 + s2];
        out[((b0g + row) * 64 + 0) * 8 + o] = acc;
    }

    // per-thread constants
    const int b14 = tid >> 7;          // GEMM1/2: batch row 0..3
    const int i14 = tid & 127;         // GEMM1/2: output index
    const unsigned yj_b  = sbase + (unsigned)offsetof(Smem, yj) + (unsigned)b14 * 256u;
    const unsigned h1_b  = sbase + (unsigned)offsetof(Smem, h1) + (unsigned)b14 * 512u;
    const unsigned w1p_i = sbase + (unsigned)offsetof(Smem, Wf1P) + (unsigned)i14 * 8u;
    const unsigned w2p_i = sbase + (unsigned)offsetof(Smem, Wf2P) + (unsigned)i14 * 8u;
    const unsigned h2b0  = sbase + (unsigned)offsetof(Smem, h2);   // + row*512 + kp*8
    const unsigned wcb   = sbase + (unsigned)offsetof(Smem, wc) + (unsigned)tid * 8u;
    const float* gW = g_Wf3P + rank * 1024 + 2 * tid;  // + kp*2048 per k-pair
    const int d0  = tid & 15;
    const int s_g = (int)rank * 32 + (tid >> 4);
    const bool writer = ((tid & 15) == 0);

    unsigned ph = 0;

    // ---- time loop: 63 steps x 6 RK stages ----
    for (int t = 0; t < 63; ++t) {
        float h = ts[t + 1] - ts[t];
        if (tid < 64) {
            int b = tid >> 4, d = tid & 15;
            int base = ((b0g + b) * 63 + t) * 16 + d;
            sm.cbv[b][d] = coeff_b[base];
            sm.ccv[b][d] = coeff_c[base];
            sm.cdv[b][d] = coeff_d[base];
        }

        #pragma unroll 1
        for (int j = 0; j < 6; ++j) {
            if (tid == 0) mbar_expect_tx(my_ksmbar, 512u);
            if (tid < 64) {  // dxdt, all 4 rows
                int b = tid >> 4, d = tid & 15;
                float fr = cC[j] * h;
                sm.dx[b][d] = sm.cbv[b][d] + fr * (2.0f * sm.ccv[b][d] + 3.0f * fr * sm.cdv[b][d]);
            }
            if (tid < 256) {  // yj, all 4 rows (plain float)
                int b = tid >> 6, s = tid & 63;
                float v = sm.y[b][s];
                #pragma unroll
                for (int m = 0; m < 5; ++m)
                    if (m < j) v += h * cA[j][m] * sm.ks[m][b][s];
                sm.yj[b][s] = v;
            }
            __syncthreads();  // S1

            // prefetch streamed Wf3 batch 0 (constant data, hides under GEMM1)
            unsigned long long wv0[6], wv1[6];
            #pragma unroll
            for (int m = 0; m < 6; ++m) wv0[m] = ldg64(gW + (KCP + m) * 2048);

            // GEMM1: all 512 threads; output (b14, i14); K=64 as 32 k-pairs
            {
                unsigned long long acc0 = 0ull, acc1 = 0ull;
                #pragma unroll
                for (int kp = 0; kp < 16; ++kp)
                    acc0 = fma2(lds64(yj_b + kp * 8u), lds64(w1p_i + kp * 1024u), acc0);
                #pragma unroll
                for (int kp = 16; kp < 32; ++kp)
                    acc1 = fma2(lds64(yj_b + kp * 8u), lds64(w1p_i + kp * 1024u), acc1);
                float2 f0 = u2f(acc0), f1 = u2f(acc1);
                sm.h1[b14][i14] = softplus_f(f0.x + f0.y + f1.x + f1.y + sm.bf1v[i14]);
            }
            __syncthreads();  // S2

            // prefetch streamed Wf3 batch 1 (hides under GEMM2)
            #pragma unroll
            for (int m = 0; m < 6; ++m) wv1[m] = ldg64(gW + (KCP + 6 + m) * 2048);

            // GEMM2: all 512 threads; output (b14, i14); K=128 as 64 k-pairs
            {
                unsigned long long acc0 = 0ull, acc1 = 0ull;
                #pragma unroll
                for (int kp = 0; kp < 32; ++kp)
                    acc0 = fma2(lds64(h1_b + kp * 8u), lds64(w2p_i + kp * 1024u), acc0);
                #pragma unroll
                for (int kp = 32; kp < 64; ++kp)
                    acc1 = fma2(lds64(h1_b + kp * 8u), lds64(w2p_i + kp * 1024u), acc1);
                float2 f0 = u2f(acc0), f1 = u2f(acc1);
                sm.h2[b14][i14] = softplus_f(f0.x + f0.y + f1.x + f1.y + sm.bf2v[i14]);
            }
            __syncthreads();  // S3: h2 (all 4 rows) visible CTA-locally

            // GEMM3: thread owns n=tid over all 4 rows; 28 cached + 36 streamed k-pairs
            unsigned long long a0 = 0, a1 = 0, a2 = 0, a3 = 0;
            #define G3_CACHED(KP0, KP1)                                              \
                {                                                                    \
                    unsigned wA = wcb + (unsigned)(KP0) * 4096u;                     \
                    unsigned hA = h2b0 + (unsigned)(KP0) * 8u;                       \
                    _Pragma("unroll")                                                \
                    for (int kp = (KP0); kp < (KP1); kp += 2) {                      \
                        unsigned long long w0 = lds64(wA);                           \
                        unsigned long long w1 = lds64(wA + 4096u);                   \
                        wA += 8192u;                                                 \
                        unsigned long long p00, p01, p10, p11, p20, p21, p30, p31;   \
                        lds_v2u64(hA,          p00, p01);                            \
                        lds_v2u64(hA + 512u,   p10, p11);                            \
                        lds_v2u64(hA + 1024u,  p20, p21);                            \
                        lds_v2u64(hA + 1536u,  p30, p31);                            \
                        hA += 16u;                                                   \
                        a0 = fma2(p00, w0, a0); a0 = fma2(p01, w1, a0);              \
                        a1 = fma2(p10, w0, a1); a1 = fma2(p11, w1, a1);              \
                        a2 = fma2(p20, w0, a2); a2 = fma2(p21, w1, a2);              \
                        a3 = fma2(p30, w0, a3); a3 = fma2(p31, w1, a3);              \
                    }                                                                \
                }
            #define G3_CONSUME(WV, Q)                                                \
                {                                                                    \
                    unsigned hA = h2b0 + (unsigned)(KCP + 6 * (Q)) * 8u;             \
                    _Pragma("unroll")                                                \
                    for (int g = 0; g < 3; ++g) {                                    \
                        unsigned long long p00, p01, p10, p11, p20, p21, p30, p31;   \
                        lds_v2u64(hA,          p00, p01);                            \
                        lds_v2u64(hA + 512u,   p10, p11);                            \
                        lds_v2u64(hA + 1024u,  p20, p21);                            \
                        lds_v2u64(hA + 1536u,  p30, p31);                            \
                        hA += 16u;                                                   \
                        a0 = fma2(p00, (WV)[2 * g], a0); a0 = fma2(p01, (WV)[2 * g + 1], a0); \
                        a1 = fma2(p10, (WV)[2 * g], a1); a1 = fma2(p11, (WV)[2 * g + 1], a1); \
                        a2 = fma2(p20, (WV)[2 * g], a2); a2 = fma2(p21, (WV)[2 * g + 1], a2); \
                        a3 = fma2(p30, (WV)[2 * g], a3); a3 = fma2(p31, (WV)[2 * g + 1], a3); \
                    }                                                                \
                }
            #define G3_ISSUE(WV, Q)                                                  \
                {                                                                    \
                    _Pragma("unroll")                                                \
                    for (int m = 0; m < 6; ++m)                                      \
                        (WV)[m] = ldg64(gW + (KCP + 6 * (Q) + m) * 2048);            \
                }

            G3_CACHED(0, 14)
            G3_CONSUME(wv0, 0)  G3_ISSUE(wv0, 2)
            G3_CACHED(14, KCP)
            G3_CONSUME(wv1, 1)  G3_ISSUE(wv1, 3)
            G3_CONSUME(wv0, 2)  G3_ISSUE(wv0, 4)
            G3_CONSUME(wv1, 3)  G3_ISSUE(wv1, 5)
            G3_CONSUME(wv0, 4)
            G3_CONSUME(wv1, 5)

            // epilogue: fold (even,odd), tanh, einsum partial, 16-lane reduce
            float bz = sm.bf3loc[tid];
            float kv[4];
            {
                unsigned long long aa[4] = {a0, a1, a2, a3};
                #pragma unroll
                for (int b = 0; b < 4; ++b) {
                    float2 f = u2f(aa[b]);
                    float v = tanh_fast(f.x + f.y + bz);
                    float pv = v * sm.dx[b][d0];
                    pv += __shfl_xor_sync(0xffffffffu, pv, 1);
                    pv += __shfl_xor_sync(0xffffffffu, pv, 2);
                    pv += __shfl_xor_sync(0xffffffffu, pv, 4);
                    pv += __shfl_xor_sync(0xffffffffu, pv, 8);
                    kv[b] = pv;
                }
            }
            if (writer) {
                #pragma unroll
                for (int b = 0; b < 4; ++b) sm.ks[j][b][s_g] = kv[b];
            }
            __syncthreads();  // S4: local ks half visible
            if (writer) {
                #pragma unroll
                for (int b = 0; b < 4; ++b) {
                    unsigned rdst = peer_ksbase + (unsigned)(((j * 4 + b) * 64) + s_g) * 4u;
                    st_async32(rdst, kv[b], peer_ksmbar);
                }
            }
            mbar_wait(my_ksmbar, ph);  // peer ks half arrived (acquire)
            ph ^= 1;
        }

        if (tid < 256) {  // y += h * sum_j B_SOL[j] * ks[j]
            int b = tid >> 6, s = tid & 63;
            float sum = 0.0f;
            #pragma unroll
            for (int j = 0; j < 6; ++j) sum += cBw[j] * sm.ks[j][b][s];
            sm.y[b][s] += h * sum;
        }
        __syncthreads();  // S5

        if (tid < 16) {  // out[:, t+1, :] for 2 local rows
            int bl = tid >> 3, o = tid & 7;
            int row = (int)rank * 2 + bl;
            float acc = br[o];
            #pragma unroll 8
            for (int s2 = 0; s2 < 64; ++s2) acc += sm.y[row][s2] * Wr[o * 64 + s2];
            out[((b0g + row) * 64 + (t + 1)) * 8 + o] = acc;
        }
    }
}

extern "C" void kernel_launch(void* const* d_in, const int* in_sizes, int n_in,
                              void* d_out, int out_size) {
    const float* ts      = (const float*)d_in[0];
    const float* coeff_d = (const float*)d_in[1];
    const float* coeff_c = (const float*)d_in[2];
    const float* coeff_b = (const float*)d_in[3];
    const float* coeff_a = (const float*)d_in[4];
    const float* Wi1 = (const float*)d_in[5];
    const float* bi1 = (const float*)d_in[6];
    const float* Wi2 = (const float*)d_in[7];
    const float* bi2 = (const float*)d_in[8];
    const float* Wf1 = (const float*)d_in[9];
    const float* bf1 = (const float*)d_in[10];
    const float* Wf2 = (const float*)d_in[11];
    const float* bf2 = (const float*)d_in[12];
    const float* Wf3 = (const float*)d_in[13];
    const float* bf3 = (const float*)d_in[14];
    const float* Wr  = (const float*)d_in[15];
    const float* br  = (const float*)d_in[16];
    float* out = (float*)d_out;

    cudaFuncSetAttribute(cde_kernel, cudaFuncAttributeMaxDynamicSharedMemorySize,
                         (int)sizeof(Smem));

    prep_kernel<<<512, PREPT>>>(Wf3);
    cde_kernel<<<128, NTHR, sizeof(Smem)>>>(ts, coeff_d, coeff_c, coeff_b, coeff_a,
                                            Wi1, bi1, Wi2, bi2, Wf1, bf1, Wf2, bf2,
                                            bf3, Wr, br, out);
}

// round 9
// speedup vs baseline: 1.0893x; 1.0893x over previous
#include <cuda_runtime.h>
#include <math.h>
#include <cstddef>

// B=256, T=64, D=16, S=64, H=128, O=8
#define NTHR 256
#define KC   56   // k-rows of the Wf3 half cached in SMEM (of 128)

// Pre-transposed Wf3: g_Wf3T[k*1024+n] = Wf3[n*128+k]  (512 KB, L2-resident)
__device__ __align__(16) float g_Wf3T[128 * 1024];

__constant__ float cC[6]  = {0.0f, 0.161f, 0.327f, 0.9f, 0.9800255409045097f, 1.0f};
__constant__ float cBw[6] = {0.09646076681806523f, 0.01f, 0.4798896504144996f,
                             1.379008574103742f, -3.290069515436081f, 2.324710524099774f};
__constant__ float cA[6][5] = {
    {0.f, 0.f, 0.f, 0.f, 0.f},
    {0.161f, 0.f, 0.f, 0.f, 0.f},
    {-0.008480655492356989f, 0.335480655492357f, 0.f, 0.f, 0.f},
    {2.8971530571054935f, -6.359448489975075f, 4.3622954328695815f, 0.f, 0.f},
    {5.325864828439257f, -11.748883564062828f, 7.4955393428898365f, -0.09249506636175525f, 0.f},
    {5.86145544294642f, -12.92096931784711f, 8.159367898576159f, -0.071584973281401f,
     -0.028269050394068383f}};

struct Smem {
    float wc[KC * 512];               // cached Wf3 half: [k][n_local], 114688 B
    float Wf2T[128 * 128];            // [k][i]
    float Wf1T[64 * 128];             // [s][i]
    unsigned long long h2d[4][128];   // dup-pair h2, ALL 4 rows (exchanged)
    unsigned long long h1d[2][128];   // dup-pair h1, 2 local rows
    unsigned long long yjd[2][64];    // dup-pair yj, 2 local rows
    float y[4][64];                   // replicated
    float ks[6][4][64];               // replicated (via exchange)
    float dx[4][16];
    float cbv[4][16];
    float ccv[4][16];
    float cdv[4][16];
    float bf1v[128];
    float bf2v[128];
    float bf3loc[512];                // bias slice for this CTA's n-half
    unsigned long long h2_mbar;
    unsigned long long ks_mbar;
};  // total 231440 B

// ---------- helpers ----------
__device__ __forceinline__ unsigned long long fma2(unsigned long long a,
                                                   unsigned long long b,
                                                   unsigned long long c) {
    unsigned long long d;
    asm("fma.rn.f32x2 %0, %1, %2, %3;" : "=l"(d) : "l"(a), "l"(b), "l"(c));
    return d;
}
__device__ __forceinline__ unsigned long long dup2(float v) {
    unsigned long long r;
    asm("mov.b64 %0, {%1, %1};" : "=l"(r) : "f"(v));
    return r;
}
__device__ __forceinline__ float2 u2f(unsigned long long v) {
    float2 r;
    asm("mov.b64 {%0, %1}, %2;" : "=f"(r.x), "=f"(r.y) : "l"(v));
    return r;
}
__device__ __forceinline__ unsigned long long ldg64(const float* p) {
    unsigned long long v;
    asm("ld.global.nc.u64 %0, [%1];" : "=l"(v) : "l"(p));
    return v;
}
__device__ __forceinline__ unsigned smem_u32(const void* p) {
    unsigned r;
    asm("{ .reg .u64 t; cvta.to.shared.u64 t, %1; cvt.u32.u64 %0, t; }"
        : "=r"(r) : "l"(p));
    return r;
}
__device__ __forceinline__ unsigned long long lds64(unsigned a) {
    unsigned long long v;
    asm("ld.shared.u64 %0, [%1];" : "=l"(v) : "r"(a));
    return v;
}
// volatile: h2 tile reads must stay after the mbarrier wait
__device__ __forceinline__ void lds_v2u64(unsigned a, unsigned long long& x,
                                          unsigned long long& y) {
    asm volatile("ld.shared.v2.u64 {%0, %1}, [%2];" : "=l"(x), "=l"(y) : "r"(a));
}
__device__ __forceinline__ unsigned mapa_u32(unsigned laddr, unsigned peer) {
    unsigned r;
    asm("mapa.shared::cluster.u32 %0, %1, %2;" : "=r"(r) : "r"(laddr), "r"(peer));
    return r;
}
__device__ __forceinline__ void mbar_init(unsigned a, unsigned cnt) {
    asm volatile("mbarrier.init.shared.b64 [%0], %1;" :: "r"(a), "r"(cnt) : "memory");
}
__device__ __forceinline__ void mbar_expect_tx(unsigned a, unsigned bytes) {
    asm volatile("mbarrier.arrive.expect_tx.shared.b64 _, [%0], %1;"
                 :: "r"(a), "r"(bytes) : "memory");
}
__device__ __forceinline__ void mbar_wait(unsigned a, unsigned parity) {
    asm volatile(
        "{\n\t.reg .pred P;\n"
        "LW_%=:\n\t"
        "mbarrier.try_wait.parity.acquire.cta.shared::cta.b64 P, [%0], %1, 0x989680;\n\t"
        "@P bra LD_%=;\n\t"
        "bra LW_%=;\n"
        "LD_%=:\n\t}"
        :: "r"(a), "r"(parity) : "memory");
}
__device__ __forceinline__ void st_async64(unsigned dst, unsigned long long v, unsigned mbar) {
    asm volatile("st.async.shared::cluster.mbarrier::complete_tx::bytes.b64 [%0], %1, [%2];"
                 :: "r"(dst), "l"(v), "r"(mbar) : "memory");
}
__device__ __forceinline__ void st_async32(unsigned dst, float v, unsigned mbar) {
    asm volatile("st.async.shared::cluster.mbarrier::complete_tx::bytes.b32 [%0], %1, [%2];"
                 :: "r"(dst), "f"(v), "r"(mbar) : "memory");
}
__device__ __forceinline__ void bar_sync_128() {
    asm volatile("bar.sync 1, 128;" ::: "memory");
}
__device__ __forceinline__ float softplus_f(float x) {
    return fmaxf(x, 0.0f) + log1pf(__expf(-fabsf(x)));
}
__device__ __forceinline__ float tanh_fast(float x) {
    float e = __expf(2.0f * x);
    return 1.0f - 2.0f / (e + 1.0f);
}

// GEMM3 streamed-weight pipeline helpers (weights constant -> free to issue early)
__device__ __forceinline__ void g3_issue(unsigned long long* wv, const float* gW, int q) {
    const float* gq = gW + (KC + 8 * q) * 1024;
    #pragma unroll
    for (int i = 0; i < 8; ++i) wv[i] = ldg64(gq + i * 1024);
}
__device__ __forceinline__ void g3_consume(const unsigned long long* wv, unsigned h2_addr, int q,
                                           unsigned long long& a0, unsigned long long& a1,
                                           unsigned long long& a2, unsigned long long& a3) {
    unsigned hk0 = h2_addr + (unsigned)(KC + 8 * q) * 8u;
    #pragma unroll
    for (int kk = 0; kk < 8; kk += 2) {
        unsigned hk = hk0 + (unsigned)kk * 8u;
        unsigned long long h0x, h0y, h1x, h1y, h2x, h2y, h3x, h3y;
        lds_v2u64(hk,          h0x, h0y);
        lds_v2u64(hk + 1024u,  h1x, h1y);
        lds_v2u64(hk + 2048u,  h2x, h2y);
        lds_v2u64(hk + 3072u,  h3x, h3y);
        a0 = fma2(h0x, wv[kk], a0); a0 = fma2(h0y, wv[kk + 1], a0);
        a1 = fma2(h1x, wv[kk], a1); a1 = fma2(h1y, wv[kk + 1], a1);
        a2 = fma2(h2x, wv[kk], a2); a2 = fma2(h2y, wv[kk + 1], a2);
        a3 = fma2(h3x, wv[kk], a3); a3 = fma2(h3y, wv[kk + 1], a3);
    }
}
__device__ __forceinline__ void g3_cached(unsigned wc_addr0, unsigned h2_addr, int k0, int k1,
                                          unsigned long long& a0, unsigned long long& a1,
                                          unsigned long long& a2, unsigned long long& a3) {
    unsigned wA = wc_addr0 + (unsigned)k0 * 2048u;
    unsigned hA = h2_addr + (unsigned)k0 * 8u;
    #pragma unroll 7
    for (int k = k0; k < k1; k += 2) {
        unsigned long long w0 = lds64(wA);
        unsigned long long w1 = lds64(wA + 2048u);
        wA += 4096u;
        unsigned long long h0x, h0y, h1x, h1y, h2x, h2y, h3x, h3y;
        lds_v2u64(hA,          h0x, h0y);
        lds_v2u64(hA + 1024u,  h1x, h1y);
        lds_v2u64(hA + 2048u,  h2x, h2y);
        lds_v2u64(hA + 3072u,  h3x, h3y);
        hA += 16u;
        a0 = fma2(h0x, w0, a0); a0 = fma2(h0y, w1, a0);
        a1 = fma2(h1x, w0, a1); a1 = fma2(h1y, w1, a1);
        a2 = fma2(h2x, w0, a2); a2 = fma2(h2y, w1, a2);
        a3 = fma2(h3x, w0, a3); a3 = fma2(h3y, w1, a3);
    }
}

__global__ void __launch_bounds__(NTHR, 1) prep_kernel(const float* __restrict__ Wf3) {
    int idx = blockIdx.x * NTHR + threadIdx.x;  // 512 blocks
    int k = idx >> 10;
    int n = idx & 1023;
    g_Wf3T[idx] = Wf3[n * 128 + k];
}

__global__ void __launch_bounds__(NTHR, 1) __cluster_dims__(2, 1, 1) cde_kernel(
    const float* __restrict__ ts,
    const float* __restrict__ coeff_d, const float* __restrict__ coeff_c,
    const float* __restrict__ coeff_b, const float* __restrict__ coeff_a,
    const float* __restrict__ Wi1, const float* __restrict__ bi1,
    const float* __restrict__ Wi2, const float* __restrict__ bi2,
    const float* __restrict__ Wf1, const float* __restrict__ bf1,
    const float* __restrict__ Wf2, const float* __restrict__ bf2,
    const float* __restrict__ bf3,
    const float* __restrict__ Wr, const float* __restrict__ br,
    float* __restrict__ out)
{
    extern __shared__ char smraw[];
    Smem& sm = *reinterpret_cast<Smem*>(smraw);
    const int tid = threadIdx.x;
    unsigned rank;
    asm("mov.u32 %0, %%cluster_ctarank;" : "=r"(rank));
    const unsigned peer = rank ^ 1u;
    const int b0g = (blockIdx.x >> 1) * 4;   // 4 batch rows per cluster

    const unsigned sbase = smem_u32(smraw);
    const unsigned off_h2  = (unsigned)offsetof(Smem, h2d);
    const unsigned off_ks  = (unsigned)offsetof(Smem, ks);
    const unsigned my_h2mbar = sbase + (unsigned)offsetof(Smem, h2_mbar);
    const unsigned my_ksmbar = sbase + (unsigned)offsetof(Smem, ks_mbar);
    const unsigned peer_h2mbar = mapa_u32(my_h2mbar, peer);
    const unsigned peer_ksmbar = mapa_u32(my_ksmbar, peer);
    const unsigned peer_h2base = mapa_u32(sbase + off_h2, peer);
    const unsigned peer_ksbase = mapa_u32(sbase + off_ks, peer);

    if (tid == 0) { mbar_init(my_h2mbar, 1); mbar_init(my_ksmbar, 1); }

    // ---- one-time init ----
    for (int idx = tid; idx < 64 * 128; idx += NTHR) {
        int s = idx >> 7, i = idx & 127;
        sm.Wf1T[idx] = Wf1[i * 64 + s];
    }
    for (int idx = tid; idx < 128 * 128; idx += NTHR) {
        int k = idx >> 7, i = idx & 127;
        sm.Wf2T[idx] = Wf2[i * 128 + k];
    }
    for (int idx = tid; idx < KC * 512; idx += NTHR) {
        int k = idx >> 9, n = idx & 511;
        sm.wc[idx] = g_Wf3T[k * 1024 + rank * 512 + n];
    }
    if (tid < 128) { sm.bf1v[tid] = bf1[tid]; sm.bf2v[tid] = bf2[tid]; }
    for (int idx = tid; idx < 512; idx += NTHR) sm.bf3loc[idx] = bf3[rank * 512 + idx];
    if (tid < 64) {  // x0 = coeff_a[:,0,:]
        int b = tid >> 4, d = tid & 15;
        sm.dx[b][d] = coeff_a[(b0g + b) * 63 * 16 + d];
    }
    __syncthreads();
    asm volatile("barrier.cluster.arrive.aligned;" ::: "memory");
    asm volatile("barrier.cluster.wait.aligned;" ::: "memory");

    // ---- y0 ----
    {
        int b = tid >> 6;
        float* h1f = reinterpret_cast<float*>(sm.h1d);
        #pragma unroll
        for (int q = 0; q < 2; ++q) {
            int j = ((tid & 63) << 1) + q;
            float acc = bi1[j];
            #pragma unroll
            for (int d = 0; d < 16; ++d) acc += sm.dx[b][d] * Wi1[j * 16 + d];
            h1f[b * 128 + j] = softplus_f(acc);
        }
    }
    __syncthreads();
    {
        int b = tid >> 6, s = tid & 63;
        const float* h1f = reinterpret_cast<const float*>(sm.h1d);
        float acc = bi2[s];
        #pragma unroll 8
        for (int k = 0; k < 128; ++k) acc += h1f[b * 128 + k] * Wi2[s * 128 + k];
        sm.y[b][s] = acc;
    }
    __syncthreads();
    if (tid < 16) {
        int bl = tid >> 3, o = tid & 7;
        int row = rank * 2 + bl;
        float acc = br[o];
        #pragma unroll 8
        for (int s2 = 0; s2 < 64; ++s2) acc += sm.y[row][s2] * Wr[o * 64 + s2];
        out[((b0g + row) * 64 + 0) * 8 + o] = acc;
    }

    // GEMM3 per-thread constants
    const unsigned wc_addr0 = sbase + (unsigned)offsetof(Smem, wc) + (unsigned)tid * 8u;
    const unsigned h2_addr  = sbase + off_h2;
    const float* gW = g_Wf3T + rank * 512 + 2 * tid;
    const int d0 = (tid & 7) << 1;
    const int s_g = (int)rank * 32 + (tid >> 3);
    const bool writer = ((tid & 7) == 0);
    const bool lower = (tid < 128);

    unsigned ph = 0;

    // ---- time loop: 63 steps x 6 RK stages ----
    for (int t = 0; t < 63; ++t) {
        float h = ts[t + 1] - ts[t];
        if (tid < 64) {
            int b = tid >> 4, d = tid & 15;
            int base = ((b0g + b) * 63 + t) * 16 + d;
            sm.cbv[b][d] = coeff_b[base];
            sm.ccv[b][d] = coeff_c[base];
            sm.cdv[b][d] = coeff_d[base];
        }

        #pragma unroll 1
        for (int j = 0; j < 6; ++j) {
            if (tid == 0) {
                mbar_expect_tx(my_h2mbar, 2048u);
                mbar_expect_tx(my_ksmbar, 512u);
            }
            if (tid < 64) {  // dxdt, all 4 rows
                int b = tid >> 4, d = tid & 15;
                float fr = cC[j] * h;
                sm.dx[b][d] = sm.cbv[b][d] + fr * (2.0f * sm.ccv[b][d] + 3.0f * fr * sm.cdv[b][d]);
            }
            if (lower) {  // yj for 2 local rows
                int bl = tid >> 6, s = tid & 63;
                int row = (int)rank * 2 + bl;
                float v = sm.y[row][s];
                #pragma unroll
                for (int m = 0; m < 5; ++m)
                    if (m < j) v += h * cA[j][m] * sm.ks[m][row][s];
                sm.yjd[bl][s] = dup2(v);
            }

            // deep prefetch: 4 streamed-weight batches issued ~900 cyc ahead
            unsigned long long wv0[8], wv1[8], wv2[8], wv3[8];
            g3_issue(wv0, gW, 0);
            g3_issue(wv1, gW, 1);
            g3_issue(wv2, gW, 2);
            g3_issue(wv3, gW, 3);

            if (lower) {
                bar_sync_128();  // S1 (warps 0-3 only; 4-7 have no hazard here)

                // GEMM1: 2 rows, K=64, 2 accumulators
                {
                    int bl = tid >> 6, pp = tid & 63;
                    const unsigned long long* w =
                        reinterpret_cast<const unsigned long long*>(sm.Wf1T);
                    unsigned long long acc0 = 0ull, acc1 = 0ull;
                    #pragma unroll 8
                    for (int s2 = 0; s2 < 32; ++s2)
                        acc0 = fma2(sm.yjd[bl][s2], w[s2 * 64 + pp], acc0);
                    #pragma unroll 8
                    for (int s2 = 32; s2 < 64; ++s2)
                        acc1 = fma2(sm.yjd[bl][s2], w[s2 * 64 + pp], acc1);
                    float2 f0 = u2f(acc0), f1 = u2f(acc1);
                    int i = pp << 1;
                    sm.h1d[bl][i]     = dup2(softplus_f(f0.x + f1.x + sm.bf1v[i]));
                    sm.h1d[bl][i + 1] = dup2(softplus_f(f0.y + f1.y + sm.bf1v[i + 1]));
                }
                bar_sync_128();  // S2

                // GEMM2: 2 rows, K=128, 4 accumulators; store local + send to peer
                {
                    int bl = tid >> 6, pp = tid & 63;
                    int row = (int)rank * 2 + bl;
                    const unsigned long long* w =
                        reinterpret_cast<const unsigned long long*>(sm.Wf2T);
                    unsigned long long acc0 = 0ull, acc1 = 0ull, acc2 = 0ull, acc3 = 0ull;
                    #pragma unroll 8
                    for (int k = 0; k < 32; ++k)
                        acc0 = fma2(sm.h1d[bl][k], w[k * 64 + pp], acc0);
                    #pragma unroll 8
                    for (int k = 32; k < 64; ++k)
                        acc1 = fma2(sm.h1d[bl][k], w[k * 64 + pp], acc1);
                    #pragma unroll 8
                    for (int k = 64; k < 96; ++k)
                        acc2 = fma2(sm.h1d[bl][k], w[k * 64 + pp], acc2);
                    #pragma unroll 8
                    for (int k = 96; k < 128; ++k)
                        acc3 = fma2(sm.h1d[bl][k], w[k * 64 + pp], acc3);
                    float2 f0 = u2f(acc0), f1 = u2f(acc1), f2 = u2f(acc2), f3 = u2f(acc3);
                    int i = pp << 1;
                    unsigned long long v0 = dup2(softplus_f((f0.x + f1.x) + (f2.x + f3.x) + sm.bf2v[i]));
                    unsigned long long v1 = dup2(softplus_f((f0.y + f1.y) + (f2.y + f3.y) + sm.bf2v[i + 1]));
                    sm.h2d[row][i]     = v0;
                    sm.h2d[row][i + 1] = v1;
                    unsigned rdst = peer_h2base + (unsigned)(row * 128 + i) * 8u;
                    st_async64(rdst,      v0, peer_h2mbar);
                    st_async64(rdst + 8u, v1, peer_h2mbar);
                }
            }
            __syncthreads();            // S3: local h2 halves visible (all warps)
            mbar_wait(my_h2mbar, ph);   // peer h2 halves arrived

            // GEMM3: 4 rows x (n-pair tid), K=128 = 56 cached + 72 streamed (9x8)
            // steady-state LDG slack: ~3 chunks (> L2 latency)
            unsigned long long a0 = 0, a1 = 0, a2 = 0, a3 = 0;
            g3_cached(wc_addr0, h2_addr, 0, 14, a0, a1, a2, a3);
            g3_consume(wv0, h2_addr, 0, a0, a1, a2, a3);  g3_issue(wv0, gW, 4);
            g3_cached(wc_addr0, h2_addr, 14, 28, a0, a1, a2, a3);
            g3_consume(wv1, h2_addr, 1, a0, a1, a2, a3);  g3_issue(wv1, gW, 5);
            g3_cached(wc_addr0, h2_addr, 28, 42, a0, a1, a2, a3);
            g3_consume(wv2, h2_addr, 2, a0, a1, a2, a3);  g3_issue(wv2, gW, 6);
            g3_cached(wc_addr0, h2_addr, 42, 56, a0, a1, a2, a3);
            g3_consume(wv3, h2_addr, 3, a0, a1, a2, a3);  g3_issue(wv3, gW, 7);
            g3_consume(wv0, h2_addr, 4, a0, a1, a2, a3);  g3_issue(wv0, gW, 8);
            g3_consume(wv1, h2_addr, 5, a0, a1, a2, a3);
            g3_consume(wv2, h2_addr, 6, a0, a1, a2, a3);
            g3_consume(wv3, h2_addr, 7, a0, a1, a2, a3);
            g3_consume(wv0, h2_addr, 8, a0, a1, a2, a3);

            // epilogue: tanh + einsum partial + 8-lane reduce
            float z0 = sm.bf3loc[2 * tid], z1 = sm.bf3loc[2 * tid + 1];
            float kv[4];
            {
                unsigned long long aa[4] = {a0, a1, a2, a3};
                #pragma unroll
                for (int b = 0; b < 4; ++b) {
                    float2 f = u2f(aa[b]);
                    float v0 = tanh_fast(f.x + z0);
                    float v1 = tanh_fast(f.y + z1);
                    float p = v0 * sm.dx[b][d0] + v1 * sm.dx[b][d0 + 1];
                    p += __shfl_xor_sync(0xffffffffu, p, 1);
                    p += __shfl_xor_sync(0xffffffffu, p, 2);
                    p += __shfl_xor_sync(0xffffffffu, p, 4);
                    kv[b] = p;
                }
            }
            if (writer) {
                #pragma unroll
                for (int b = 0; b < 4; ++b) sm.ks[j][b][s_g] = kv[b];
            }
            __syncthreads();  // S4: all GEMM3 reads of h2d done; local ks visible
            if (writer) {
                #pragma unroll
                for (int b = 0; b < 4; ++b) {
                    unsigned rdst = peer_ksbase + (unsigned)(((j * 4 + b) * 64) + s_g) * 4u;
                    st_async32(rdst, kv[b], peer_ksmbar);
                }
            }
            mbar_wait(my_ksmbar, ph);  // peer ks half arrived
            ph ^= 1;
        }

        {  // y += h * sum_j B_SOL[j] * ks[j]
            int b = tid >> 6, s = tid & 63;
            float sum = 0.0f;
            #pragma unroll
            for (int j = 0; j < 6; ++j) sum += cBw[j] * sm.ks[j][b][s];
            sm.y[b][s] += h * sum;
        }
        __syncthreads();  // S5

        if (tid < 16) {  // out[:, t+1, :]
            int bl = tid >> 3, o = tid & 7;
            int row = (int)rank * 2 + bl;
            float acc = br[o];
            #pragma unroll 8
            for (int s2 = 0; s2 < 64; ++s2) acc += sm.y[row][s2] * Wr[o * 64 + s2];
            out[((b0g + row) * 64 + (t + 1)) * 8 + o] = acc;
        }
    }
}

extern "C" void kernel_launch(void* const* d_in, const int* in_sizes, int n_in,
                              void* d_out, int out_size) {
    const float* ts      = (const float*)d_in[0];
    const float* coeff_d = (const float*)d_in[1];
    const float* coeff_c = (const float*)d_in[2];
    const float* coeff_b = (const float*)d_in[3];
    const float* coeff_a = (const float*)d_in[4];
    const float* Wi1 = (const float*)d_in[5];
    const float* bi1 = (const float*)d_in[6];
    const float* Wi2 = (const float*)d_in[7];
    const float* bi2 = (const float*)d_in[8];
    const float* Wf1 = (const float*)d_in[9];
    const float* bf1 = (const float*)d_in[10];
    const float* Wf2 = (const float*)d_in[11];
    const float* bf2 = (const float*)d_in[12];
    const float* Wf3 = (const float*)d_in[13];
    const float* bf3 = (const float*)d_in[14];
    const float* Wr  = (const float*)d_in[15];
    const float* br  = (const float*)d_in[16];
    float* out = (float*)d_out;

    cudaFuncSetAttribute(cde_kernel, cudaFuncAttributeMaxDynamicSharedMemorySize,
                         (int)sizeof(Smem));

    prep_kernel<<<512, NTHR>>>(Wf3);
    cde_kernel<<<128, NTHR, sizeof(Smem)>>>(ts, coeff_d, coeff_c, coeff_b, coeff_a,
                                            Wi1, bi1, Wi2, bi2, Wf1, bf1, Wf2, bf2,
                                            bf3, Wr, br, out);
}

// round 10
// speedup vs baseline: 1.4536x; 1.3344x over previous
#include <cuda_runtime.h>
#include <math.h>
#include <cstddef>

// B=256, T=64, D=16, S=64, H=128, O=8
#define NTHR 256
#define PREPT 256
#define QC 28     // cached k-pairs (56 k-rows) of this CTA's Wf3 n-half

// Pair-packed Wf3: g_Wf3P[(q*1024 + n)*2 + r] = Wf3[n*128 + 2*q + r]  (512 KB)
__device__ __align__(16) float g_Wf3P[64 * 1024 * 2];

__constant__ float cC[6]  = {0.0f, 0.161f, 0.327f, 0.9f, 0.9800255409045097f, 1.0f};
__constant__ float cBw[6] = {0.09646076681806523f, 0.01f, 0.4798896504144996f,
                             1.379008574103742f, -3.290069515436081f, 2.324710524099774f};
__constant__ float cA[6][5] = {
    {0.f, 0.f, 0.f, 0.f, 0.f},
    {0.161f, 0.f, 0.f, 0.f, 0.f},
    {-0.008480655492356989f, 0.335480655492357f, 0.f, 0.f, 0.f},
    {2.8971530571054935f, -6.359448489975075f, 4.3622954328695815f, 0.f, 0.f},
    {5.325864828439257f, -11.748883564062828f, 7.4955393428898365f, -0.09249506636175525f, 0.f},
    {5.86145544294642f, -12.92096931784711f, 8.159367898576159f, -0.071584973281401f,
     -0.028269050394068383f}};

struct __align__(16) Smem {
    float wc[QC * 512 * 2];    // cached Wf3 pairs [q][n_local][2]   114688 B
    float Wf2P[64 * 128 * 2];  // [q][i][2]                           65536 B
    float Wf1P[32 * 128 * 2];  // [q][i][2]                           32768 B
    float h2[4][128];          // plain, all 4 rows (peer half exch)   2048 B
    float h1[2][128];          // plain, 2 local rows                  1024 B
    float yj[2][64];           // plain, 2 local rows                   512 B
    float y[4][64];            //                                      1024 B
    float ks[6][4][64];        //                                      6144 B
    float dx[4][16];
    float cbv[4][16];
    float ccv[4][16];
    float cdv[4][16];
    float bf1v[128];
    float bf2v[128];
    float bf3loc[512];
    unsigned long long h2_mbar;
    unsigned long long ks_mbar;
};  // 227856 B

// ---------- helpers ----------
__device__ __forceinline__ unsigned long long fma2(unsigned long long a,
                                                   unsigned long long b,
                                                   unsigned long long c) {
    unsigned long long d;
    asm("fma.rn.f32x2 %0, %1, %2, %3;" : "=l"(d) : "l"(a), "l"(b), "l"(c));
    return d;
}
__device__ __forceinline__ float2 u2f(unsigned long long v) {
    float2 r;
    asm("mov.b64 {%0, %1}, %2;" : "=f"(r.x), "=f"(r.y) : "l"(v));
    return r;
}
__device__ __forceinline__ void ldg128(const float* p, unsigned long long& a,
                                       unsigned long long& b) {
    asm("ld.global.nc.v2.u64 {%0, %1}, [%2];" : "=l"(a), "=l"(b) : "l"(p));
}
__device__ __forceinline__ unsigned smem_u32(const void* p) {
    unsigned r;
    asm("{ .reg .u64 t; cvta.to.shared.u64 t, %1; cvt.u32.u64 %0, t; }"
        : "=r"(r) : "l"(p));
    return r;
}
__device__ __forceinline__ unsigned long long lds64(unsigned a) {
    unsigned long long v;
    asm("ld.shared.u64 %0, [%1];" : "=l"(v) : "r"(a));
    return v;
}
// volatile: activation reads must stay after barriers / mbar waits
__device__ __forceinline__ void lds_v2u64(unsigned a, unsigned long long& x,
                                          unsigned long long& y) {
    asm volatile("ld.shared.v2.u64 {%0, %1}, [%2];" : "=l"(x), "=l"(y) : "r"(a));
}
__device__ __forceinline__ unsigned mapa_u32(unsigned laddr, unsigned peer) {
    unsigned r;
    asm("mapa.shared::cluster.u32 %0, %1, %2;" : "=r"(r) : "r"(laddr), "r"(peer));
    return r;
}
__device__ __forceinline__ void mbar_init(unsigned a, unsigned cnt) {
    asm volatile("mbarrier.init.shared.b64 [%0], %1;" :: "r"(a), "r"(cnt) : "memory");
}
__device__ __forceinline__ void mbar_expect_tx(unsigned a, unsigned bytes) {
    asm volatile("mbarrier.arrive.expect_tx.shared.b64 _, [%0], %1;"
                 :: "r"(a), "r"(bytes) : "memory");
}
__device__ __forceinline__ void mbar_wait(unsigned a, unsigned parity) {
    asm volatile(
        "{\n\t.reg .pred P;\n"
        "LW_%=:\n\t"
        "mbarrier.try_wait.parity.acquire.cta.shared::cta.b64 P, [%0], %1, 0x989680;\n\t"
        "@P bra LD_%=;\n\t"
        "bra LW_%=;\n"
        "LD_%=:\n\t}"
        :: "r"(a), "r"(parity) : "memory");
}
__device__ __forceinline__ void st_async32(unsigned dst, float v, unsigned mbar) {
    asm volatile("st.async.shared::cluster.mbarrier::complete_tx::bytes.b32 [%0], %1, [%2];"
                 :: "r"(dst), "f"(v), "r"(mbar) : "memory");
}
__device__ __forceinline__ float softplus_f(float x) {
    return fmaxf(x, 0.0f) + log1pf(__expf(-fabsf(x)));
}
__device__ __forceinline__ float tanh_fast(float x) {
    float e = __expf(2.0f * x);
    return 1.0f - 2.0f / (e + 1.0f);
}

__global__ void __launch_bounds__(PREPT, 1) prep_kernel(const float* __restrict__ Wf3) {
    int idx = blockIdx.x * PREPT + threadIdx.x;   // 512 x 256 = 131072
    int q = idx >> 11;
    int rem = idx & 2047;
    int n = rem >> 1;
    int r = rem & 1;
    g_Wf3P[idx] = Wf3[n * 128 + 2 * q + r];
}

__global__ void __launch_bounds__(NTHR, 1) __cluster_dims__(2, 1, 1) cde_kernel(
    const float* __restrict__ ts,
    const float* __restrict__ coeff_d, const float* __restrict__ coeff_c,
    const float* __restrict__ coeff_b, const float* __restrict__ coeff_a,
    const float* __restrict__ Wi1, const float* __restrict__ bi1,
    const float* __restrict__ Wi2, const float* __restrict__ bi2,
    const float* __restrict__ Wf1, const float* __restrict__ bf1,
    const float* __restrict__ Wf2, const float* __restrict__ bf2,
    const float* __restrict__ bf3,
    const float* __restrict__ Wr, const float* __restrict__ br,
    float* __restrict__ out)
{
    extern __shared__ char smraw[];
    Smem& sm = *reinterpret_cast<Smem*>(smraw);
    const int tid = threadIdx.x;
    unsigned rank;
    asm("mov.u32 %0, %%cluster_ctarank;" : "=r"(rank));
    const unsigned peer = rank ^ 1u;
    const int b0g = (blockIdx.x >> 1) * 4;

    const unsigned sbase = smem_u32(smraw);
    const unsigned off_h2 = (unsigned)offsetof(Smem, h2);
    const unsigned off_ks = (unsigned)offsetof(Smem, ks);
    const unsigned my_h2mbar = sbase + (unsigned)offsetof(Smem, h2_mbar);
    const unsigned my_ksmbar = sbase + (unsigned)offsetof(Smem, ks_mbar);
    const unsigned peer_h2mbar = mapa_u32(my_h2mbar, peer);
    const unsigned peer_ksmbar = mapa_u32(my_ksmbar, peer);
    const unsigned peer_h2base = mapa_u32(sbase + off_h2, peer);
    const unsigned peer_ksbase = mapa_u32(sbase + off_ks, peer);

    if (tid == 0) { mbar_init(my_h2mbar, 1); mbar_init(my_ksmbar, 1); }

    // ---- one-time init ----
    // Wf1P[(q*128+i)*2+r] = Wf1[i*64 + 2q + r]
    for (int idx = tid; idx < 32 * 128 * 2; idx += NTHR) {
        int q = idx >> 8, rem = idx & 255, i = rem >> 1, r = rem & 1;
        sm.Wf1P[idx] = Wf1[i * 64 + 2 * q + r];
    }
    // Wf2P[(q*128+i)*2+r] = Wf2[i*128 + 2q + r]
    for (int idx = tid; idx < 64 * 128 * 2; idx += NTHR) {
        int q = idx >> 8, rem = idx & 255, i = rem >> 1, r = rem & 1;
        sm.Wf2P[idx] = Wf2[i * 128 + 2 * q + r];
    }
    // wc[q][n_local][2] from g_Wf3P (this CTA's n-half)
    for (int idx = tid; idx < QC * 1024; idx += NTHR) {
        int q = idx >> 10, rem = idx & 1023;
        sm.wc[idx] = g_Wf3P[q * 2048 + rank * 1024 + rem];
    }
    if (tid < 128) { sm.bf1v[tid] = bf1[tid]; sm.bf2v[tid] = bf2[tid]; }
    for (int idx = tid; idx < 512; idx += NTHR) sm.bf3loc[idx] = bf3[rank * 512 + idx];
    if (tid < 64) {  // x0 = coeff_a[:,0,:]
        int b = tid >> 4, d = tid & 15;
        sm.dx[b][d] = coeff_a[(b0g + b) * 63 * 16 + d];
    }
    __syncthreads();
    asm volatile("barrier.cluster.arrive.aligned;" ::: "memory");
    asm volatile("barrier.cluster.wait.aligned;" ::: "memory");

    // ---- y0 = softplus(x0 @ Wi1^T + bi1) @ Wi2^T + bi2  (h2 as scratch) ----
    {
        int b = tid >> 6;
        #pragma unroll
        for (int qq = 0; qq < 2; ++qq) {
            int jj = ((tid & 63) << 1) + qq;
            float acc = bi1[jj];
            #pragma unroll
            for (int d = 0; d < 16; ++d) acc += sm.dx[b][d] * Wi1[jj * 16 + d];
            sm.h2[b][jj] = softplus_f(acc);
        }
    }
    __syncthreads();
    {
        int b = tid >> 6, s = tid & 63;
        float acc = bi2[s];
        #pragma unroll 8
        for (int k = 0; k < 128; ++k) acc += sm.h2[b][k] * Wi2[s * 128 + k];
        sm.y[b][s] = acc;
    }
    __syncthreads();
    if (tid < 16) {
        int bl = tid >> 3, o = tid & 7;
        int row = (int)rank * 2 + bl;
        float acc = br[o];
        #pragma unroll 8
        for (int s2 = 0; s2 < 64; ++s2) acc += sm.y[row][s2] * Wr[o * 64 + s2];
        out[((b0g + row) * 64 + 0) * 8 + o] = acc;
    }

    // per-thread constants
    const int bl14 = tid >> 7;          // GEMM1/2: local row 0/1
    const int i14  = tid & 127;         // GEMM1/2: output index
    const int row14 = (int)rank * 2 + bl14;
    const unsigned yj_b  = sbase + (unsigned)offsetof(Smem, yj) + (unsigned)bl14 * 256u;
    const unsigned h1_b  = sbase + (unsigned)offsetof(Smem, h1) + (unsigned)bl14 * 512u;
    const unsigned w1_i  = sbase + (unsigned)offsetof(Smem, Wf1P) + (unsigned)i14 * 8u;
    const unsigned w2_i  = sbase + (unsigned)offsetof(Smem, Wf2P) + (unsigned)i14 * 8u;
    const unsigned h2b   = sbase + off_h2;                         // + row*512 + q*8
    const unsigned wcb   = sbase + (unsigned)offsetof(Smem, wc) + (unsigned)tid * 16u;
    const float* gW = g_Wf3P + (rank * 512 + 2 * tid) * 2;         // + q*2048 floats
    const int d0  = (tid & 7) << 1;
    const int s_g = (int)rank * 32 + (tid >> 3);
    const bool writer = ((tid & 7) == 0);

    unsigned ph = 0;

    // ---- time loop: 63 steps x 6 RK stages ----
    for (int t = 0; t < 63; ++t) {
        float h = ts[t + 1] - ts[t];
        if (tid < 64) {
            int b = tid >> 4, d = tid & 15;
            int base = ((b0g + b) * 63 + t) * 16 + d;
            sm.cbv[b][d] = coeff_b[base];
            sm.ccv[b][d] = coeff_c[base];
            sm.cdv[b][d] = coeff_d[base];
        }

        #pragma unroll 1
        for (int j = 0; j < 6; ++j) {
            if (tid == 0) {
                mbar_expect_tx(my_h2mbar, 1024u);
                mbar_expect_tx(my_ksmbar, 512u);
            }
            if (tid < 64) {  // dxdt, all 4 rows
                int b = tid >> 4, d = tid & 15;
                float fr = cC[j] * h;
                sm.dx[b][d] = sm.cbv[b][d] + fr * (2.0f * sm.ccv[b][d] + 3.0f * fr * sm.cdv[b][d]);
            }
            if (tid < 128) {  // yj for 2 local rows (plain float)
                int bl = tid >> 6, s = tid & 63;
                int row = (int)rank * 2 + bl;
                float v = sm.y[row][s];
                #pragma unroll
                for (int m = 0; m < 5; ++m)
                    if (m < j) v += h * cA[j][m] * sm.ks[m][row][s];
                sm.yj[bl][s] = v;
            }

            // prefetch 4 streamed Wf3 batches (constant data; hides under GEMM1/2)
            // batch b covers q = QC + 4b .. +3; wv[2m]=w[q0+m][n0], wv[2m+1]=w[q0+m][n1]
            unsigned long long wvA[8], wvB[8], wvC[8], wvD[8];
            #define G3_ISSUE(WV, B)                                                   \
                {                                                                     \
                    const float* gq = gW + (QC + 4 * (B)) * 2048;                     \
                    _Pragma("unroll")                                                 \
                    for (int m = 0; m < 4; ++m)                                       \
                        ldg128(gq + m * 2048, (WV)[2 * m], (WV)[2 * m + 1]);          \
                }
            G3_ISSUE(wvA, 0)
            G3_ISSUE(wvB, 1)
            G3_ISSUE(wvC, 2)
            G3_ISSUE(wvD, 3)

            __syncthreads();  // S1

            // GEMM1: all 256 threads; output (bl14, i14); K=64 = 32 q, k-packed
            {
                unsigned long long acc0 = 0ull, acc1 = 0ull;
                #pragma unroll
                for (int q = 0; q < 32; q += 2) {
                    unsigned long long hx, hy;
                    lds_v2u64(yj_b + (unsigned)q * 8u, hx, hy);
                    acc0 = fma2(hx, lds64(w1_i + (unsigned)q * 1024u), acc0);
                    acc1 = fma2(hy, lds64(w1_i + (unsigned)(q + 1) * 1024u), acc1);
                }
                float2 f0 = u2f(acc0), f1 = u2f(acc1);
                sm.h1[bl14][i14] = softplus_f((f0.x + f0.y) + (f1.x + f1.y) + sm.bf1v[i14]);
            }
            __syncthreads();  // S2

            // GEMM2: all 256 threads; output (bl14, i14); K=128 = 64 q, k-packed
            {
                unsigned long long acc0 = 0ull, acc1 = 0ull;
                #pragma unroll
                for (int q = 0; q < 64; q += 2) {
                    unsigned long long hx, hy;
                    lds_v2u64(h1_b + (unsigned)q * 8u, hx, hy);
                    acc0 = fma2(hx, lds64(w2_i + (unsigned)q * 1024u), acc0);
                    acc1 = fma2(hy, lds64(w2_i + (unsigned)(q + 1) * 1024u), acc1);
                }
                float2 f0 = u2f(acc0), f1 = u2f(acc1);
                float v = softplus_f((f0.x + f0.y) + (f1.x + f1.y) + sm.bf2v[i14]);
                sm.h2[row14][i14] = v;
                st_async32(peer_h2base + (unsigned)(row14 * 128 + i14) * 4u, v, peer_h2mbar);
            }
            __syncthreads();            // S3: local h2 rows visible
            mbar_wait(my_h2mbar, ph);   // peer h2 rows arrived

            // GEMM3: thread owns n0=2tid, n0+1 (local), 4 rows; K=128 = 64 q
            // accs: a{r}{0,1} k-parity-packed; fold in epilogue
            unsigned long long a00 = 0, a01 = 0, a10 = 0, a11 = 0;
            unsigned long long a20 = 0, a21 = 0, a30 = 0, a31 = 0;
            #define G3_STEP(HX, HY, W00, W01, W10, W11, R0, R1)                       \
                {                                                                     \
                    R0 = fma2(HX, W00, R0); R0 = fma2(HY, W10, R0);                   \
                    R1 = fma2(HX, W01, R1); R1 = fma2(HY, W11, R1);                   \
                }
            #define G3_CACHED(Q0, Q1)                                                 \
                {                                                                     \
                    _Pragma("unroll")                                                 \
                    for (int q = (Q0); q < (Q1); q += 2) {                            \
                        unsigned long long w00, w01, w10, w11;                        \
                        lds_v2u64(wcb + (unsigned)q * 4096u, w00, w01);               \
                        lds_v2u64(wcb + (unsigned)(q + 1) * 4096u, w10, w11);         \
                        unsigned long long h0x, h0y, h1x, h1y, h2x, h2y, h3x, h3y;    \
                        lds_v2u64(h2b +           (unsigned)q * 8u, h0x, h0y);        \
                        lds_v2u64(h2b + 512u  +   (unsigned)q * 8u, h1x, h1y);        \
                        lds_v2u64(h2b + 1024u +   (unsigned)q * 8u, h2x, h2y);        \
                        lds_v2u64(h2b + 1536u +   (unsigned)q * 8u, h3x, h3y);        \
                        G3_STEP(h0x, h0y, w00, w01, w10, w11, a00, a01)               \
                        G3_STEP(h1x, h1y, w00, w01, w10, w11, a10, a11)               \
                        G3_STEP(h2x, h2y, w00, w01, w10, w11, a20, a21)               \
                        G3_STEP(h3x, h3y, w00, w01, w10, w11, a30, a31)               \
                    }                                                                 \
                }
            #define G3_CONSUME(WV, B)                                                 \
                {                                                                     \
                    _Pragma("unroll")                                                 \
                    for (int jj = 0; jj < 2; ++jj) {                                  \
                        int q = QC + 4 * (B) + 2 * jj;                                \
                        unsigned long long h0x, h0y, h1x, h1y, h2x, h2y, h3x, h3y;    \
                        lds_v2u64(h2b +           (unsigned)q * 8u, h0x, h0y);        \
                        lds_v2u64(h2b + 512u  +   (unsigned)q * 8u, h1x, h1y);        \
                        lds_v2u64(h2b + 1024u +   (unsigned)q * 8u, h2x, h2y);        \
                        lds_v2u64(h2b + 1536u +   (unsigned)q * 8u, h3x, h3y);        \
                        unsigned long long w00 = (WV)[4 * jj],     w01 = (WV)[4 * jj + 1]; \
                        unsigned long long w10 = (WV)[4 * jj + 2], w11 = (WV)[4 * jj + 3]; \
                        G3_STEP(h0x, h0y, w00, w01, w10, w11, a00, a01)               \
                        G3_STEP(h1x, h1y, w00, w01, w10, w11, a10, a11)               \
                        G3_STEP(h2x, h2y, w00, w01, w10, w11, a20, a21)               \
                        G3_STEP(h3x, h3y, w00, w01, w10, w11, a30, a31)               \
                    }                                                                 \
                }
            // schedule: 9 streamed batches (q=28..63), pipeline depth 4
            G3_CACHED(0, 14)
            G3_CONSUME(wvA, 0)  G3_ISSUE(wvA, 4)
            G3_CACHED(14, QC)
            G3_CONSUME(wvB, 1)  G3_ISSUE(wvB, 5)
            G3_CONSUME(wvC, 2)  G3_ISSUE(wvC, 6)
            G3_CONSUME(wvD, 3)  G3_ISSUE(wvD, 7)
            G3_CONSUME(wvA, 4)  G3_ISSUE(wvA, 8)
            G3_CONSUME(wvB, 5)
            G3_CONSUME(wvC, 6)
            G3_CONSUME(wvD, 7)
            G3_CONSUME(wvA, 8)

            // epilogue: fold k-parity, tanh, einsum partial, 8-lane reduce
            float z0 = sm.bf3loc[2 * tid], z1 = sm.bf3loc[2 * tid + 1];
            float kv[4];
            {
                unsigned long long aa0[4] = {a00, a10, a20, a30};
                unsigned long long aa1[4] = {a01, a11, a21, a31};
                #pragma unroll
                for (int b = 0; b < 4; ++b) {
                    float2 f0 = u2f(aa0[b]);
                    float2 f1 = u2f(aa1[b]);
                    float v0 = tanh_fast(f0.x + f0.y + z0);
                    float v1 = tanh_fast(f1.x + f1.y + z1);
                    float p = v0 * sm.dx[b][d0] + v1 * sm.dx[b][d0 + 1];
                    p += __shfl_xor_sync(0xffffffffu, p, 1);
                    p += __shfl_xor_sync(0xffffffffu, p, 2);
                    p += __shfl_xor_sync(0xffffffffu, p, 4);
                    kv[b] = p;
                }
            }
            if (writer) {
                #pragma unroll
                for (int b = 0; b < 4; ++b) sm.ks[j][b][s_g] = kv[b];
            }
            __syncthreads();  // S4: all GEMM3 reads of h2 done; local ks visible
            if (writer) {
                #pragma unroll
                for (int b = 0; b < 4; ++b) {
                    unsigned rdst = peer_ksbase + (unsigned)(((j * 4 + b) * 64) + s_g) * 4u;
                    st_async32(rdst, kv[b], peer_ksmbar);
                }
            }
            mbar_wait(my_ksmbar, ph);  // peer ks half arrived
            ph ^= 1;
        }

        {  // y += h * sum_j B_SOL[j] * ks[j]
            int b = tid >> 6, s = tid & 63;
            float sum = 0.0f;
            #pragma unroll
            for (int j = 0; j < 6; ++j) sum += cBw[j] * sm.ks[j][b][s];
            sm.y[b][s] += h * sum;
        }
        __syncthreads();  // S5

        if (tid < 16) {  // out[:, t+1, :] for 2 local rows
            int bl = tid >> 3, o = tid & 7;
            int row = (int)rank * 2 + bl;
            float acc = br[o];
            #pragma unroll 8
            for (int s2 = 0; s2 < 64; ++s2) acc += sm.y[row][s2] * Wr[o * 64 + s2];
            out[((b0g + row) * 64 + (t + 1)) * 8 + o] = acc;
        }
    }
}

extern "C" void kernel_launch(void* const* d_in, const int* in_sizes, int n_in,
                              void* d_out, int out_size) {
    const float* ts      = (const float*)d_in[0];
    const float* coeff_d = (const float*)d_in[1];
    const float* coeff_c = (const float*)d_in[2];
    const float* coeff_b = (const float*)d_in[3];
    const float* coeff_a = (const float*)d_in[4];
    const float* Wi1 = (const float*)d_in[5];
    const float* bi1 = (const float*)d_in[6];
    const float* Wi2 = (const float*)d_in[7];
    const float* bi2 = (const float*)d_in[8];
    const float* Wf1 = (const float*)d_in[9];
    const float* bf1 = (const float*)d_in[10];
    const float* Wf2 = (const float*)d_in[11];
    const float* bf2 = (const float*)d_in[12];
    const float* Wf3 = (const float*)d_in[13];
    const float* bf3 = (const float*)d_in[14];
    const float* Wr  = (const float*)d_in[15];
    const float* br  = (const float*)d_in[16];
    float* out = (float*)d_out;

    cudaFuncSetAttribute(cde_kernel, cudaFuncAttributeMaxDynamicSharedMemorySize,
                         (int)sizeof(Smem));

    prep_kernel<<<512, PREPT>>>(Wf3);
    cde_kernel<<<128, NTHR, sizeof(Smem)>>>(ts, coeff_d, coeff_c, coeff_b, coeff_a,
                                            Wi1, bi1, Wi2, bi2, Wf1, bf1, Wf2, bf2,
                                            bf3, Wr, br, out);
}